// round 1
// baseline (speedup 1.0000x reference)
#include <cuda_runtime.h>

// ---------------------------------------------------------------------------
// Problem constants
// ---------------------------------------------------------------------------
#define TB    64          // batch
#define TSEQ  469         // sequence length (234 + 234 + 1)
#define NH    16          // heads
#define HD    64          // head dim
#define CDIM  1024        // channels
#define MROWS (TB * TSEQ) // 30016 rows for the GEMMs

// ---------------------------------------------------------------------------
// Scratch (device globals: no cudaMalloc allowed)
// ---------------------------------------------------------------------------
__device__ float g_q[(size_t)TB * NH * TSEQ * HD]; // (B,H,T,hd)
__device__ float g_k[(size_t)TB * NH * TSEQ * HD];
__device__ float g_v[(size_t)TB * NH * TSEQ * HD];
__device__ float g_y[(size_t)TB * TSEQ * CDIM];    // attention output (B*T, C)

// ---------------------------------------------------------------------------
// 128x128x8 register-tiled SGEMM.
//   mode == 1 : C = A @ W + bias scattered into g_q/g_k/g_v (B,H,T,hd) layout
//   mode == 0 : C = A @ W + bias written row-major to Cout
// If A == nullptr, A is taken from g_y (proj GEMM input).
// ---------------------------------------------------------------------------
__global__ __launch_bounds__(256) void sgemm128(
    const float* __restrict__ A, const float* __restrict__ B,
    const float* __restrict__ bias, float* __restrict__ Cout,
    int M, int N, int K, int mode)
{
    __shared__ float As[8][128];
    __shared__ float Bs[8][128];

    const float* Abase = A ? A : (const float*)g_y;

    const int tid = threadIdx.x;
    const int bm = blockIdx.y << 7;
    const int bn = blockIdx.x << 7;
    const int tx = tid & 15;
    const int ty = tid >> 4;

    // A tile load mapping: 128 rows x 8 cols, one float4 per thread
    const int arow = tid >> 1;
    const int acol = (tid & 1) << 2;
    // B tile load mapping: 8 rows x 128 cols, one float4 per thread
    const int brow = tid >> 5;
    const int bcol = (tid & 31) << 2;

    int am = bm + arow;
    if (am > M - 1) am = M - 1;        // clamp: OOB rows computed but never stored
    const float* Ap = Abase + (size_t)am * K + acol;
    const float* Bp = B + (size_t)brow * N + bn + bcol;

    float acc[8][8];
#pragma unroll
    for (int i = 0; i < 8; i++)
#pragma unroll
        for (int j = 0; j < 8; j++) acc[i][j] = 0.f;

    for (int k0 = 0; k0 < K; k0 += 8) {
        float4 av = *(const float4*)Ap;
        As[acol + 0][arow] = av.x;
        As[acol + 1][arow] = av.y;
        As[acol + 2][arow] = av.z;
        As[acol + 3][arow] = av.w;
        *(float4*)&Bs[brow][bcol] = *(const float4*)Bp;
        __syncthreads();

#pragma unroll
        for (int kk = 0; kk < 8; kk++) {
            float ar[8], br[8];
            *(float4*)(ar + 0) = *(const float4*)&As[kk][(ty << 2)];
            *(float4*)(ar + 4) = *(const float4*)&As[kk][64 + (ty << 2)];
            *(float4*)(br + 0) = *(const float4*)&Bs[kk][(tx << 2)];
            *(float4*)(br + 4) = *(const float4*)&Bs[kk][64 + (tx << 2)];
#pragma unroll
            for (int i = 0; i < 8; i++)
#pragma unroll
                for (int j = 0; j < 8; j++)
                    acc[i][j] += ar[i] * br[j];
        }
        __syncthreads();
        Ap += 8;
        Bp += (size_t)8 * N;
    }

    int rows[8], cols[8];
#pragma unroll
    for (int i = 0; i < 4; i++) {
        rows[i]     = bm + (ty << 2) + i;
        rows[i + 4] = bm + 64 + (ty << 2) + i;
        cols[i]     = bn + (tx << 2) + i;
        cols[i + 4] = bn + 64 + (tx << 2) + i;
    }
    float bv[8];
#pragma unroll
    for (int j = 0; j < 8; j++) bv[j] = bias[cols[j]];

    if (mode == 1) {
        // scatter qkv:  n -> (which, head, d);  m -> (b, t)
#pragma unroll
        for (int i = 0; i < 8; i++) {
            int m = rows[i];
            if (m >= M) continue;
            int bb = m / TSEQ;
            int t  = m - bb * TSEQ;
#pragma unroll
            for (int j = 0; j < 8; j++) {
                int n = cols[j];
                int which = n >> 10;
                int c = n & 1023;
                int hh = c >> 6;
                int d  = c & 63;
                float val = acc[i][j] + bv[j];
                size_t idx = (((size_t)bb * NH + hh) * TSEQ + t) * HD + d;
                if (which == 0)      g_q[idx] = val;
                else if (which == 1) g_k[idx] = val;
                else                 g_v[idx] = val;
            }
        }
    } else {
#pragma unroll
        for (int i = 0; i < 8; i++) {
            int m = rows[i];
            if (m >= M) continue;
#pragma unroll
            for (int j = 0; j < 8; j++)
                Cout[(size_t)m * N + cols[j]] = acc[i][j] + bv[j];
        }
    }
}

// ---------------------------------------------------------------------------
// Fused attention. Grid: (qtile=8, head=16, batch=64), 256 threads.
// Each block handles one (b, h) and 64 query rows, streaming K/V in 64-row
// tiles with online softmax. Additive cross mask computed analytically:
//   bias(i,j) = 1 if i==0 or j==0 or seg(i)!=seg(j) else 0,
//   seg(t) = 0 for t in [1,234], 1 for t in [235,468].
// ---------------------------------------------------------------------------
__device__ __forceinline__ int seg_of(int t) {
    return (t == 0) ? -1 : (t <= 234 ? 0 : 1);
}

__global__ __launch_bounds__(256) void attn_kernel()
{
    __shared__ float Qs[64][64];
    __shared__ float Ks[64][64];   // rotation-swizzled: phys col = (d + j) & 63
    __shared__ float Vs[64][64];

    const int tid  = threadIdx.x;
    const int lane = tid & 31;
    const int warp = tid >> 5;
    const int qt = blockIdx.x;
    const int h  = blockIdx.y;
    const int b  = blockIdx.z;

    const size_t bh = ((size_t)b * NH + h) * TSEQ;
    const float* Qg = g_q + bh * HD;
    const float* Kg = g_k + bh * HD;
    const float* Vg = g_v + bh * HD;

    // load Q tile (zero-fill OOB rows; they are computed but never stored)
    for (int idx = tid; idx < 64 * 64; idx += 256) {
        int i = idx >> 6, d = idx & 63;
        int t = (qt << 6) + i;
        Qs[i][d] = (t < TSEQ) ? Qg[(size_t)t * HD + d] : 0.f;
    }

    const int r0 = warp << 3;          // warp owns q rows r0..r0+7
    const int c0 = lane, c1 = lane + 32; // lane owns key cols c0, c1 (and out dims)

    float mrow[8], lrow[8], a0[8], a1[8];
#pragma unroll
    for (int i = 0; i < 8; i++) { mrow[i] = -1e30f; lrow[i] = 0.f; a0[i] = 0.f; a1[i] = 0.f; }

    int segq[8];
#pragma unroll
    for (int i = 0; i < 8; i++) segq[i] = seg_of((qt << 6) + r0 + i);

    for (int kt = 0; kt < 8; kt++) {
        const int kbase = kt << 6;
        const int nk = min(64, TSEQ - kbase);

        __syncthreads();  // previous iteration's Vs/Ks reads complete
        for (int idx = tid; idx < 64 * 64; idx += 256) {
            int j = idx >> 6, d = idx & 63;
            float kv = 0.f, vv = 0.f;
            if (j < nk) {
                size_t off = (size_t)(kbase + j) * HD + d;
                kv = Kg[off];
                vv = Vg[off];
            }
            Ks[j][(d + j) & 63] = kv;   // swizzled store (conflict-free)
            Vs[j][d] = vv;
        }
        __syncthreads();

        // S = Q K^T : lane computes cols c0,c1 for its warp's 8 rows
        float s0[8], s1[8];
#pragma unroll
        for (int i = 0; i < 8; i++) { s0[i] = 0.f; s1[i] = 0.f; }
#pragma unroll 8
        for (int d = 0; d < 64; d++) {
            float k0 = Ks[c0][(d + c0) & 63];  // swizzled read (conflict-free)
            float k1 = Ks[c1][(d + c1) & 63];
#pragma unroll
            for (int i = 0; i < 8; i++) {
                float q = Qs[r0 + i][d];       // broadcast
                s0[i] += q * k0;
                s1[i] += q * k1;
            }
        }

        const int segk0 = seg_of(kbase + c0);
        const int segk1 = seg_of(kbase + c1);
        const bool v0 = (c0 < nk), v1 = (c1 < nk);

        // online softmax: fold bias, update m/l, convert s -> p in place
#pragma unroll
        for (int i = 0; i < 8; i++) {
            float bias0 = (segq[i] < 0 || segk0 < 0 || segq[i] != segk0) ? 1.f : 0.f;
            float bias1 = (segq[i] < 0 || segk1 < 0 || segq[i] != segk1) ? 1.f : 0.f;
            float sc0 = v0 ? (s0[i] * 0.125f + bias0) : -1e30f;
            float sc1 = v1 ? (s1[i] * 0.125f + bias1) : -1e30f;
            float tmax = fmaxf(sc0, sc1);
#pragma unroll
            for (int o = 16; o > 0; o >>= 1)
                tmax = fmaxf(tmax, __shfl_xor_sync(0xffffffffu, tmax, o));
            float mn   = fmaxf(mrow[i], tmax);
            float corr = __expf(mrow[i] - mn);
            float p0 = __expf(sc0 - mn);
            float p1 = __expf(sc1 - mn);
            float ps = p0 + p1;
#pragma unroll
            for (int o = 16; o > 0; o >>= 1)
                ps += __shfl_xor_sync(0xffffffffu, ps, o);
            lrow[i] = lrow[i] * corr + ps;
            mrow[i] = mn;
            a0[i] *= corr;
            a1[i] *= corr;
            s0[i] = p0;   // reuse as p
            s1[i] = p1;
        }

        // PV: V loads hoisted over rows; p broadcast via shuffle
#pragma unroll 4
        for (int j = 0; j < 32; j++) {
            float va = Vs[j][c0];
            float vb = Vs[j][c1];
            float vc = Vs[j + 32][c0];
            float vd = Vs[j + 32][c1];
#pragma unroll
            for (int i = 0; i < 8; i++) {
                float pa = __shfl_sync(0xffffffffu, s0[i], j);
                float pb = __shfl_sync(0xffffffffu, s1[i], j);
                a0[i] += pa * va + pb * vc;
                a1[i] += pa * vb + pb * vd;
            }
        }
    }

    // finalize: y = acc / l, written in (B*T, C) layout for the proj GEMM
#pragma unroll
    for (int i = 0; i < 8; i++) {
        int t = (qt << 6) + r0 + i;
        if (t < TSEQ) {
            float inv = 1.f / lrow[i];
            size_t base = ((size_t)b * TSEQ + t) * CDIM + (h << 6);
            g_y[base + c0] = a0[i] * inv;
            g_y[base + c1] = a1[i] * inv;
        }
    }
}

// ---------------------------------------------------------------------------
// kernel_launch: QKV GEMM -> attention -> proj GEMM (default stream, ordered)
// ---------------------------------------------------------------------------
extern "C" void kernel_launch(void* const* d_in, const int* in_sizes, int n_in,
                              void* d_out, int out_size)
{
    (void)in_sizes; (void)n_in; (void)out_size;
    const float* x      = (const float*)d_in[0];
    const float* W_attn = (const float*)d_in[1];
    const float* b_attn = (const float*)d_in[2];
    const float* W_proj = (const float*)d_in[3];
    const float* b_proj = (const float*)d_in[4];
    float* out = (float*)d_out;

    const int M = MROWS;           // 30016
    const int mtiles = (M + 127) / 128;  // 235

    // 1) qkv = x @ W_attn + b_attn, scattered to (B,H,T,hd)
    dim3 g1(3 * CDIM / 128, mtiles);
    sgemm128<<<g1, 256>>>(x, W_attn, b_attn, nullptr, M, 3 * CDIM, CDIM, 1);

    // 2) fused attention -> g_y (B*T, C)
    dim3 g2((TSEQ + 63) / 64, NH, TB);
    attn_kernel<<<g2, 256>>>();

    // 3) out = y @ W_proj + b_proj
    dim3 g3(CDIM / 128, mtiles);
    sgemm128<<<g3, 256>>>(nullptr, W_proj, b_proj, out, M, CDIM, CDIM, 0);
}

// round 2
// speedup vs baseline: 1.3928x; 1.3928x over previous
#include <cuda_runtime.h>
#include <cuda_bf16.h>

// ---------------------------------------------------------------------------
// Problem constants
// ---------------------------------------------------------------------------
#define TB    64          // batch
#define TSEQ  469         // sequence length (234 + 234 + 1)
#define NH    16          // heads
#define HD    64          // head dim
#define CDIM  1024        // channels
#define MROWS (TB * TSEQ) // 30016 rows for the GEMMs

// ---------------------------------------------------------------------------
// Scratch (device globals: no cudaMalloc allowed)
// ---------------------------------------------------------------------------
__device__ float g_q[(size_t)TB * NH * TSEQ * HD]; // (B,H,T,hd)
__device__ float g_k[(size_t)TB * NH * TSEQ * HD];
__device__ float g_v[(size_t)TB * NH * TSEQ * HD];
__device__ float g_y[(size_t)TB * TSEQ * CDIM];    // attention output (B*T, C)

// ---------------------------------------------------------------------------
// bf16 split helpers: v ~= hi + lo with ~16-bit effective mantissa
// ---------------------------------------------------------------------------
__device__ __forceinline__ void split_bf16(float v, __nv_bfloat16& hi, __nv_bfloat16& lo) {
    hi = __float2bfloat16(v);
    lo = __float2bfloat16(v - __bfloat162float(hi));
}

__device__ __forceinline__ void mma_bf16(float* c, const unsigned* a, const unsigned* b) {
    asm volatile(
        "mma.sync.aligned.m16n8k16.row.col.f32.bf16.bf16.f32 "
        "{%0,%1,%2,%3}, {%4,%5,%6,%7}, {%8,%9}, {%0,%1,%2,%3};\n"
        : "+f"(c[0]), "+f"(c[1]), "+f"(c[2]), "+f"(c[3])
        : "r"(a[0]), "r"(a[1]), "r"(a[2]), "r"(a[3]),
          "r"(b[0]), "r"(b[1]));
}

// ---------------------------------------------------------------------------
// Tensor-core GEMM: C = A @ B + bias, fp32 in/out, split-bf16 x3 internally.
// Block tile 128x128x32, 256 threads = 8 warps (4 m-warps x 2 n-warps),
// warp tile 32x64 (2 x m16 tiles, 8 x n8 tiles).
//   mode == 1 : scatter into g_q/g_k/g_v (B,H,T,hd) layout
//   mode == 0 : row-major store to Cout
// If A == nullptr, A is taken from g_y.
// ---------------------------------------------------------------------------
#define BKP 34   // padded K extent of smem tiles (bf16 elements)

__global__ __launch_bounds__(256) void tc_gemm(
    const float* __restrict__ A, const float* __restrict__ B,
    const float* __restrict__ bias, float* __restrict__ Cout,
    int M, int N, int K, int mode)
{
    __shared__ __align__(16) __nv_bfloat16 As_hi[128][BKP];
    __shared__ __align__(16) __nv_bfloat16 As_lo[128][BKP];
    __shared__ __align__(16) __nv_bfloat16 Bs_hi[128][BKP];
    __shared__ __align__(16) __nv_bfloat16 Bs_lo[128][BKP];

    const float* Abase = A ? A : (const float*)g_y;

    const int tid  = threadIdx.x;
    const int lane = tid & 31;
    const int w    = tid >> 5;
    const int wm   = w & 3;        // 4 m-warps
    const int wn   = w >> 2;       // 2 n-warps
    const int g    = lane >> 2;    // group id 0..7
    const int t2   = (lane & 3) << 1;

    const int bm = blockIdx.y << 7;
    const int bn = blockIdx.x << 7;

    float acc[2][8][4];
#pragma unroll
    for (int i = 0; i < 2; i++)
#pragma unroll
        for (int j = 0; j < 8; j++)
#pragma unroll
            for (int e = 0; e < 4; e++) acc[i][j][e] = 0.f;

    for (int k0 = 0; k0 < K; k0 += 32) {
        __syncthreads();
        // ---- load A tile: 128 rows x 32 k (fp32 -> hi/lo bf16) ----
#pragma unroll
        for (int r = 0; r < 4; r++) {
            int l   = tid + (r << 8);       // 0..1023 float4 slots
            int row = l >> 3;               // 8 float4 per row
            int kc  = (l & 7) << 2;
            int gm  = bm + row;
            if (gm > M - 1) gm = M - 1;     // clamp; OOB rows never stored
            float4 v = *(const float4*)(Abase + (size_t)gm * K + k0 + kc);
            __nv_bfloat16 h0, l0, h1, l1, h2, l2, h3, l3;
            split_bf16(v.x, h0, l0); split_bf16(v.y, h1, l1);
            split_bf16(v.z, h2, l2); split_bf16(v.w, h3, l3);
            As_hi[row][kc+0] = h0; As_hi[row][kc+1] = h1;
            As_hi[row][kc+2] = h2; As_hi[row][kc+3] = h3;
            As_lo[row][kc+0] = l0; As_lo[row][kc+1] = l1;
            As_lo[row][kc+2] = l2; As_lo[row][kc+3] = l3;
        }
        // ---- load B tile: 32 k-rows x 128 n, transposed to [n][k] ----
#pragma unroll
        for (int r = 0; r < 4; r++) {
            int l    = tid + (r << 8);
            int krow = l >> 5;              // 32 float4 per k-row
            int nc   = (l & 31) << 2;
            float4 v = *(const float4*)(B + (size_t)(k0 + krow) * N + bn + nc);
            __nv_bfloat16 h, lo;
            split_bf16(v.x, h, lo); Bs_hi[nc+0][krow] = h; Bs_lo[nc+0][krow] = lo;
            split_bf16(v.y, h, lo); Bs_hi[nc+1][krow] = h; Bs_lo[nc+1][krow] = lo;
            split_bf16(v.z, h, lo); Bs_hi[nc+2][krow] = h; Bs_lo[nc+2][krow] = lo;
            split_bf16(v.w, h, lo); Bs_hi[nc+3][krow] = h; Bs_lo[nc+3][krow] = lo;
        }
        __syncthreads();

        // ---- compute: 2 k16 steps ----
#pragma unroll
        for (int kk = 0; kk < 32; kk += 16) {
            unsigned ahi[2][4], alo[2][4];
#pragma unroll
            for (int i = 0; i < 2; i++) {
                int m0 = (wm << 5) + (i << 4);
                ahi[i][0] = *(const unsigned*)&As_hi[m0 + g    ][kk + t2    ];
                ahi[i][1] = *(const unsigned*)&As_hi[m0 + g + 8][kk + t2    ];
                ahi[i][2] = *(const unsigned*)&As_hi[m0 + g    ][kk + t2 + 8];
                ahi[i][3] = *(const unsigned*)&As_hi[m0 + g + 8][kk + t2 + 8];
                alo[i][0] = *(const unsigned*)&As_lo[m0 + g    ][kk + t2    ];
                alo[i][1] = *(const unsigned*)&As_lo[m0 + g + 8][kk + t2    ];
                alo[i][2] = *(const unsigned*)&As_lo[m0 + g    ][kk + t2 + 8];
                alo[i][3] = *(const unsigned*)&As_lo[m0 + g + 8][kk + t2 + 8];
            }
            unsigned bhi[8][2], blo[8][2];
#pragma unroll
            for (int j = 0; j < 8; j++) {
                int n0 = (wn << 6) + (j << 3);
                bhi[j][0] = *(const unsigned*)&Bs_hi[n0 + g][kk + t2    ];
                bhi[j][1] = *(const unsigned*)&Bs_hi[n0 + g][kk + t2 + 8];
                blo[j][0] = *(const unsigned*)&Bs_lo[n0 + g][kk + t2    ];
                blo[j][1] = *(const unsigned*)&Bs_lo[n0 + g][kk + t2 + 8];
            }
#pragma unroll
            for (int i = 0; i < 2; i++)
#pragma unroll
                for (int j = 0; j < 8; j++) {
                    mma_bf16(acc[i][j], ahi[i], bhi[j]);
                    mma_bf16(acc[i][j], ahi[i], blo[j]);
                    mma_bf16(acc[i][j], alo[i], bhi[j]);
                }
        }
    }

    // ---- epilogue ----
#pragma unroll
    for (int i = 0; i < 2; i++) {
        int rbase = bm + (wm << 5) + (i << 4);
#pragma unroll
        for (int j = 0; j < 8; j++) {
            int cbase = bn + (wn << 6) + (j << 3) + t2;
            float bv0 = bias[cbase], bv1 = bias[cbase + 1];
            int r0 = rbase + g, r1 = rbase + g + 8;
            float v00 = acc[i][j][0] + bv0, v01 = acc[i][j][1] + bv1;
            float v10 = acc[i][j][2] + bv0, v11 = acc[i][j][3] + bv1;
            if (mode == 0) {
                if (r0 < M) { float2 p = {v00, v01}; *(float2*)&Cout[(size_t)r0 * N + cbase] = p; }
                if (r1 < M) { float2 p = {v10, v11}; *(float2*)&Cout[(size_t)r1 * N + cbase] = p; }
            } else {
                int which = cbase >> 10;
                int c  = cbase & 1023;
                int hh = c >> 6;
                int d  = c & 63;
                float* dst = (which == 0) ? g_q : (which == 1) ? g_k : g_v;
                if (r0 < M) {
                    int bb = r0 / TSEQ, t = r0 - bb * TSEQ;
                    size_t idx = (((size_t)bb * NH + hh) * TSEQ + t) * HD + d;
                    dst[idx] = v00; dst[idx + 1] = v01;
                }
                if (r1 < M) {
                    int bb = r1 / TSEQ, t = r1 - bb * TSEQ;
                    size_t idx = (((size_t)bb * NH + hh) * TSEQ + t) * HD + d;
                    dst[idx] = v10; dst[idx + 1] = v11;
                }
            }
        }
    }
}

// ---------------------------------------------------------------------------
// Fused attention (unchanged from round 1). Grid: (qtile=8, head=16, batch=64),
// 256 threads. Additive cross mask computed analytically.
// ---------------------------------------------------------------------------
__device__ __forceinline__ int seg_of(int t) {
    return (t == 0) ? -1 : (t <= 234 ? 0 : 1);
}

__global__ __launch_bounds__(256) void attn_kernel()
{
    __shared__ float Qs[64][64];
    __shared__ float Ks[64][64];   // rotation-swizzled: phys col = (d + j) & 63
    __shared__ float Vs[64][64];

    const int tid  = threadIdx.x;
    const int lane = tid & 31;
    const int warp = tid >> 5;
    const int qt = blockIdx.x;
    const int h  = blockIdx.y;
    const int b  = blockIdx.z;

    const size_t bh = ((size_t)b * NH + h) * TSEQ;
    const float* Qg = g_q + bh * HD;
    const float* Kg = g_k + bh * HD;
    const float* Vg = g_v + bh * HD;

    for (int idx = tid; idx < 64 * 64; idx += 256) {
        int i = idx >> 6, d = idx & 63;
        int t = (qt << 6) + i;
        Qs[i][d] = (t < TSEQ) ? Qg[(size_t)t * HD + d] : 0.f;
    }

    const int r0 = warp << 3;
    const int c0 = lane, c1 = lane + 32;

    float mrow[8], lrow[8], a0[8], a1[8];
#pragma unroll
    for (int i = 0; i < 8; i++) { mrow[i] = -1e30f; lrow[i] = 0.f; a0[i] = 0.f; a1[i] = 0.f; }

    int segq[8];
#pragma unroll
    for (int i = 0; i < 8; i++) segq[i] = seg_of((qt << 6) + r0 + i);

    for (int kt = 0; kt < 8; kt++) {
        const int kbase = kt << 6;
        const int nk = min(64, TSEQ - kbase);

        __syncthreads();
        for (int idx = tid; idx < 64 * 64; idx += 256) {
            int j = idx >> 6, d = idx & 63;
            float kv = 0.f, vv = 0.f;
            if (j < nk) {
                size_t off = (size_t)(kbase + j) * HD + d;
                kv = Kg[off];
                vv = Vg[off];
            }
            Ks[j][(d + j) & 63] = kv;
            Vs[j][d] = vv;
        }
        __syncthreads();

        float s0[8], s1[8];
#pragma unroll
        for (int i = 0; i < 8; i++) { s0[i] = 0.f; s1[i] = 0.f; }
#pragma unroll 8
        for (int d = 0; d < 64; d++) {
            float k0 = Ks[c0][(d + c0) & 63];
            float k1 = Ks[c1][(d + c1) & 63];
#pragma unroll
            for (int i = 0; i < 8; i++) {
                float q = Qs[r0 + i][d];
                s0[i] += q * k0;
                s1[i] += q * k1;
            }
        }

        const int segk0 = seg_of(kbase + c0);
        const int segk1 = seg_of(kbase + c1);
        const bool v0 = (c0 < nk), v1 = (c1 < nk);

#pragma unroll
        for (int i = 0; i < 8; i++) {
            float bias0 = (segq[i] < 0 || segk0 < 0 || segq[i] != segk0) ? 1.f : 0.f;
            float bias1 = (segq[i] < 0 || segk1 < 0 || segq[i] != segk1) ? 1.f : 0.f;
            float sc0 = v0 ? (s0[i] * 0.125f + bias0) : -1e30f;
            float sc1 = v1 ? (s1[i] * 0.125f + bias1) : -1e30f;
            float tmax = fmaxf(sc0, sc1);
#pragma unroll
            for (int o = 16; o > 0; o >>= 1)
                tmax = fmaxf(tmax, __shfl_xor_sync(0xffffffffu, tmax, o));
            float mn   = fmaxf(mrow[i], tmax);
            float corr = __expf(mrow[i] - mn);
            float p0 = __expf(sc0 - mn);
            float p1 = __expf(sc1 - mn);
            float ps = p0 + p1;
#pragma unroll
            for (int o = 16; o > 0; o >>= 1)
                ps += __shfl_xor_sync(0xffffffffu, ps, o);
            lrow[i] = lrow[i] * corr + ps;
            mrow[i] = mn;
            a0[i] *= corr;
            a1[i] *= corr;
            s0[i] = p0;
            s1[i] = p1;
        }

#pragma unroll 4
        for (int j = 0; j < 32; j++) {
            float va = Vs[j][c0];
            float vb = Vs[j][c1];
            float vc = Vs[j + 32][c0];
            float vd = Vs[j + 32][c1];
#pragma unroll
            for (int i = 0; i < 8; i++) {
                float pa = __shfl_sync(0xffffffffu, s0[i], j);
                float pb = __shfl_sync(0xffffffffu, s1[i], j);
                a0[i] += pa * va + pb * vc;
                a1[i] += pa * vb + pb * vd;
            }
        }
    }

#pragma unroll
    for (int i = 0; i < 8; i++) {
        int t = (qt << 6) + r0 + i;
        if (t < TSEQ) {
            float inv = 1.f / lrow[i];
            size_t base = ((size_t)b * TSEQ + t) * CDIM + (h << 6);
            g_y[base + c0] = a0[i] * inv;
            g_y[base + c1] = a1[i] * inv;
        }
    }
}

// ---------------------------------------------------------------------------
// kernel_launch: QKV GEMM -> attention -> proj GEMM (default stream, ordered)
// ---------------------------------------------------------------------------
extern "C" void kernel_launch(void* const* d_in, const int* in_sizes, int n_in,
                              void* d_out, int out_size)
{
    (void)in_sizes; (void)n_in; (void)out_size;
    const float* x      = (const float*)d_in[0];
    const float* W_attn = (const float*)d_in[1];
    const float* b_attn = (const float*)d_in[2];
    const float* W_proj = (const float*)d_in[3];
    const float* b_proj = (const float*)d_in[4];
    float* out = (float*)d_out;

    const int M = MROWS;                 // 30016
    const int mtiles = (M + 127) / 128;  // 235

    dim3 g1(3 * CDIM / 128, mtiles);
    tc_gemm<<<g1, 256>>>(x, W_attn, b_attn, nullptr, M, 3 * CDIM, CDIM, 1);

    dim3 g2((TSEQ + 63) / 64, NH, TB);
    attn_kernel<<<g2, 256>>>();

    dim3 g3(CDIM / 128, mtiles);
    tc_gemm<<<g3, 256>>>(nullptr, W_proj, b_proj, out, M, CDIM, CDIM, 0);
}